// round 6
// baseline (speedup 1.0000x reference)
#include <cuda_runtime.h>
#include <math.h>

#define NPTS   16384
#define BATCH  2
#define HBEV   200
#define WBEV   176
#define CBEV   256
#define HW     (HBEV*WBEV)
#define KTOT   2048
#define NROWS  (BATCH*KTOT)
#define CMPN   8192
#define FULLM  0xffffffffu
#define SCANBLK 128

// ---------------- static device scratch ----------------
__device__ float4 g_pts[BATCH*NPTS];       // SoA points: x,y,z,intensity
__device__ float  g_kp[NROWS*3];           // keypoint coords
__device__ int    g_ballidx[NROWS*32];     // [row][2][16] neighbor indices
__device__ int    g_ballcnt[NROWS*2];      // [row][2] capped counts

// ---------------- packed f32x2 + redux helpers ----------------
__device__ __forceinline__ unsigned long long pk2(float lo, float hi) {
    unsigned long long r; asm("mov.b64 %0, {%1, %2};" : "=l"(r) : "f"(lo), "f"(hi)); return r;
}
__device__ __forceinline__ void upk2(unsigned long long v, float& lo, float& hi) {
    asm("mov.b64 {%0, %1}, %2;" : "=f"(lo), "=f"(hi) : "l"(v));
}
__device__ __forceinline__ unsigned long long addx2(unsigned long long a, unsigned long long b) {
    unsigned long long r; asm("add.rn.f32x2 %0, %1, %2;" : "=l"(r) : "l"(a), "l"(b)); return r;
}
__device__ __forceinline__ unsigned long long mulx2(unsigned long long a, unsigned long long b) {
    unsigned long long r; asm("mul.rn.f32x2 %0, %1, %2;" : "=l"(r) : "l"(a), "l"(b)); return r;
}
__device__ __forceinline__ unsigned redux_maxu(unsigned v) {
    unsigned r; asm("redux.sync.max.u32 %0, %1, 0xffffffff;" : "=r"(r) : "r"(v)); return r;
}
__device__ __forceinline__ unsigned redux_minu(unsigned v) {
    unsigned r; asm("redux.sync.min.u32 %0, %1, 0xffffffff;" : "=r"(r) : "r"(v)); return r;
}

// ==================================================================
// FPS: compaction + sampling (blocks 0..5) + SoA prep (blocks 6..63)
// Block reduction: warp redux -> one packed-u64 smem atomicMax -> BAR -> LDS.64
// ==================================================================
template<int P>
__device__ __forceinline__ void fps_body(int b, int K, int kpbase, int M,
                                         float* __restrict__ coords_out,
                                         unsigned long long* s_win) {
    extern __shared__ float4 scmp[];
    int t = threadIdx.x;
    int lane = t & 31;

    unsigned long long Xn[P], Yn[P], Zn[P];   // negated coords
    float D[2*P];
    #pragma unroll
    for (int p = 0; p < P; p++) {
        float4 a = scmp[(2*p)*256 + t];
        float4 c = scmp[(2*p+1)*256 + t];
        Xn[p] = pk2(-a.x, -c.x); Yn[p] = pk2(-a.y, -c.y); Zn[p] = pk2(-a.z, -c.z);
        D[2*p]   = ((2*p)*256 + t   < M) ? 1e10f : -1.0f;
        D[2*p+1] = ((2*p+1)*256 + t < M) ? 1e10f : -1.0f;
    }

    int sel = 0;   // first valid point = compacted index 0
    for (int k = 0; ; k++) {
        float4 w = scmp[sel];                // LDS broadcast
        if (t == 0) {
            int r = kpbase + k;
            g_kp[r*3+0] = w.x; g_kp[r*3+1] = w.y; g_kp[r*3+2] = w.z;
            coords_out[r*4+0] = (float)b;
            coords_out[r*4+1] = w.x; coords_out[r*4+2] = w.y; coords_out[r*4+3] = w.z;
        }
        if (k == K-1) break;

        unsigned long long wx = pk2(w.x, w.x);
        unsigned long long wy = pk2(w.y, w.y);
        unsigned long long wz = pk2(w.z, w.z);
        float best = -1.0f; int bi = 0x7fffffff;
        #pragma unroll
        for (int p = 0; p < P; p++) {
            unsigned long long dx = addx2(Xn[p], wx);   // (w-x): square == (x-w)^2 exactly
            unsigned long long dy = addx2(Yn[p], wy);
            unsigned long long dz = addx2(Zn[p], wz);
            unsigned long long d2 = addx2(addx2(mulx2(dx,dx), mulx2(dy,dy)), mulx2(dz,dz));
            float dl, dh; upk2(d2, dl, dh);
            float n0 = fminf(D[2*p],   dl); D[2*p]   = n0;
            float n1 = fminf(D[2*p+1], dh); D[2*p+1] = n1;
            // ascending slot order + strict '>' keeps smallest index on intra-thread ties
            if (n0 > best) { best = n0; bi = (2*p)*256 + t; }
            if (n1 > best) { best = n1; bi = (2*p+1)*256 + t; }
        }
        best = fmaxf(best, 0.0f);             // invalid threads: best=0, bi stays huge
        unsigned u  = __float_as_uint(best);  // d>=0 => bits order-isomorphic
        unsigned vm = redux_maxu(u);
        unsigned cand = (u == vm) ? (unsigned)bi : 0x7fffffffu;
        unsigned im = redux_minu(cand);
        int slot = k % 3;
        if (lane == 0)
            atomicMax(&s_win[slot], ((unsigned long long)vm << 32) | (unsigned)(~im));
        __syncthreads();
        unsigned long long pw = s_win[slot];
        if (t == 0) s_win[(k+2) % 3] = 0ull;  // re-arm slot used two iterations ago
        sel = (int)(~(unsigned)(pw & 0xffffffffu));
    }
}

__global__ void __launch_bounds__(256,1) fps_kernel(const float* __restrict__ pts,
                                                    const float* __restrict__ rng,
                                                    float* __restrict__ coords_out) {
    extern __shared__ float4 scmp[];
    __shared__ unsigned long long s_win[3];
    __shared__ int wsum[8];
    __shared__ int s_tot;

    int t = threadIdx.x;
    if (blockIdx.x >= 6) {
        // ---- SoA prep on otherwise-idle SMs ----
        for (int i = ((int)blockIdx.x - 6)*256 + t; i < BATCH*NPTS; i += 58*256) {
            const float* p = pts + (size_t)i*5;
            g_pts[i] = make_float4(p[1], p[2], p[3], p[4]);
        }
        return;
    }

    int run = blockIdx.x, b = run/3, band = run - b*3;
    int lane = t & 31, warp = t >> 5;
    if (t < 3) s_win[t] = 0ull;

    // ---- stable band compaction: 64 points per thread (contiguous) ----
    const float4* R4 = (const float4*)(rng + (size_t)b*NPTS) + t*16;
    unsigned long long bits = 0; int cnt = 0;
    #pragma unroll
    for (int q = 0; q < 16; q++) {
        float4 r4 = R4[q];
        float rr[4] = {r4.x, r4.y, r4.z, r4.w};
        #pragma unroll
        for (int u = 0; u < 4; u++) {
            float r = rr[u];
            bool sh = (r > 0.0f) && (r < 25.0f);
            bool lg = (r > 45.0f);
            bool v = (band == 0) ? sh : ((band == 2) ? lg : (!lg && !sh));
            if (v) { bits |= (1ull << (q*4+u)); cnt++; }
        }
    }
    int inc = cnt;
    #pragma unroll
    for (int off = 1; off < 32; off <<= 1) {
        int o = __shfl_up_sync(FULLM, inc, off);
        if (lane >= off) inc += o;
    }
    if (lane == 31) wsum[warp] = inc;
    __syncthreads();
    if (warp == 0 && lane < 8) {
        int v = wsum[lane];
        #pragma unroll
        for (int off = 1; off < 8; off <<= 1) {
            int o = __shfl_up_sync(0xffu, v, off);
            if (lane >= off) v += o;
        }
        wsum[lane] = v;
        if (lane == 7) s_tot = v;
    }
    __syncthreads();
    int off0 = inc - cnt + (warp ? wsum[warp-1] : 0);
    const float* PP = pts + (size_t)b*NPTS*5;
    for (int u = 0; u < 64; u++) {
        if ((bits >> u) & 1ull) {
            if (off0 < CMPN) {
                const float* p = PP + (size_t)(t*64 + u)*5;
                scmp[off0] = make_float4(p[1], p[2], p[3], p[4]);
            }
            off0++;
        }
    }
    int M = min(s_tot, CMPN);
    for (int i = M + t; i < CMPN; i += 256)
        scmp[i] = make_float4(1e15f, 1e15f, 1e15f, 0.f);
    __syncthreads();

    // ---- FPS dispatch sized to the band population ----
    int K = (band == 0) ? 1024 : 512;
    int kpbase = b*KTOT + (band==0 ? 0 : (band==1 ? 1024 : 1536));
    int P = min(16, ((M + 1023) >> 10) * 2);   // even, 512*P >= M
    switch (P) {
        case 2:  fps_body<2>(b, K, kpbase, M, coords_out, s_win); break;
        case 4:  fps_body<4>(b, K, kpbase, M, coords_out, s_win); break;
        case 6:  fps_body<6>(b, K, kpbase, M, coords_out, s_win); break;
        case 8:  fps_body<8>(b, K, kpbase, M, coords_out, s_win); break;
        case 10: fps_body<10>(b, K, kpbase, M, coords_out, s_win); break;
        case 12: fps_body<12>(b, K, kpbase, M, coords_out, s_win); break;
        case 14: fps_body<14>(b, K, kpbase, M, coords_out, s_win); break;
        default: fps_body<16>(b, K, kpbase, M, coords_out, s_win); break;
    }
}

// ==================================================================
// bevscan: ball-query scan (blocks 0..127) + BEV bilinear (blocks 128..)
// co-resident: scan is LDS-bound, bev is memory-latency-bound.
// ==================================================================
__global__ void __launch_bounds__(512) bevscan_kernel(const float* __restrict__ sf,
                                                      float* __restrict__ feats) {
    __shared__ float2 sx[1024], sy[1024], sz[1024];
    __shared__ int sidx[16][2][2][16];     // [warp][kp][radius][slot]
    int tid = threadIdx.x;

    if (blockIdx.x >= SCANBLK) {
        // ---- BEV bilinear: 2 rows per block, direct CHW gather ----
        int row = ((int)blockIdx.x - SCANBLK)*2 + (tid >> 8);
        int c = tid & 255;
        int b = row >> 11;
        float kx = g_kp[row*3+0], ky = g_kp[row*3+1];
        float xi = ((kx - 0.0f)     / 0.05f) / 8.0f;
        float yi = ((ky - (-40.0f)) / 0.05f) / 8.0f;
        int x0 = (int)floorf(xi); int x1 = x0 + 1;
        int y0 = (int)floorf(yi); int y1 = y0 + 1;
        x0 = min(max(x0, 0), WBEV-1); x1 = min(max(x1, 0), WBEV-1);
        y0 = min(max(y0, 0), HBEV-1); y1 = min(max(y1, 0), HBEV-1);
        float x0f = (float)x0, x1f = (float)x1, y0f = (float)y0, y1f = (float)y1;
        float wa = (x1f - xi)*(y1f - yi);
        float wb = (x1f - xi)*(yi - y0f);
        float wc = (xi - x0f)*(y1f - yi);
        float wd = (xi - x0f)*(yi - y0f);
        const float* ch = sf + ((size_t)b*CBEV + c)*HW;
        float Ia = __ldg(ch + y0*WBEV + x0);
        float Ib = __ldg(ch + y1*WBEV + x0);
        float Ic = __ldg(ch + y0*WBEV + x1);
        float Id = __ldg(ch + y1*WBEV + x1);
        feats[(size_t)row*288 + c] = Ia*wa + Ib*wb + Ic*wc + Id*wd;
        return;
    }

    // ---- ball-query scan: 2 keypoints per warp, SoA float2 tiles ----
    int w = tid >> 5, lane = tid & 31;
    int row0 = blockIdx.x*32 + w*2;
    int b = row0 >> 11;
    const float4* P = g_pts + (size_t)b*NPTS;

    unsigned long long nkx[2], nky[2], nkz[2];
    #pragma unroll
    for (int kp = 0; kp < 2; kp++) {
        float kx = g_kp[(row0+kp)*3], ky = g_kp[(row0+kp)*3+1], kz = g_kp[(row0+kp)*3+2];
        nkx[kp] = pk2(-kx, -kx); nky[kp] = pk2(-ky, -ky); nkz[kp] = pk2(-kz, -kz);
    }
    unsigned lt  = (1u << lane) - 1u;
    unsigned lte = lt | (1u << lane);

    int c1[2] = {0,0}, c2[2] = {0,0};
    for (int base0 = 0; base0 < NPTS; base0 += 2048) {
        __syncthreads();
        #pragma unroll
        for (int i = 0; i < 2; i++) {
            int j = tid + i*512;            // float2 slot
            float4 p0 = P[base0 + 2*j];
            float4 p1 = P[base0 + 2*j + 1];
            sx[j] = make_float2(p0.x, p1.x);
            sy[j] = make_float2(p0.y, p1.y);
            sz[j] = make_float2(p0.z, p1.z);
        }
        __syncthreads();
        if (c1[0] >= 16 && c2[0] >= 16 && c1[1] >= 16 && c2[1] >= 16) continue;
        for (int o32 = 0; o32 < 1024; o32 += 32) {
            float2 vx = sx[o32 + lane], vy = sy[o32 + lane], vz = sz[o32 + lane];
            unsigned long long px = pk2(vx.x, vx.y);
            unsigned long long py = pk2(vy.x, vy.y);
            unsigned long long pz = pk2(vz.x, vz.y);
            float da[2], db[2];
            #pragma unroll
            for (int kp = 0; kp < 2; kp++) {
                unsigned long long dx = addx2(px, nkx[kp]);
                unsigned long long dy = addx2(py, nky[kp]);
                unsigned long long dz = addx2(pz, nkz[kp]);
                unsigned long long d2 = addx2(addx2(mulx2(dx,dx), mulx2(dy,dy)), mulx2(dz,dz));
                upk2(d2, da[kp], db[kp]);
            }
            bool any = (da[0] < 4.0f) || (db[0] < 4.0f) || (da[1] < 4.0f) || (db[1] < 4.0f);
            if (__ballot_sync(FULLM, any)) {
                int gi = base0 + 2*(o32 + lane);
                #pragma unroll
                for (int kp = 0; kp < 2; kp++) {
                    bool v2a = da[kp] < 4.0f, v2b = db[kp] < 4.0f;
                    bool v1a = da[kp] < 1.0f, v1b = db[kp] < 1.0f;
                    unsigned m1e = __ballot_sync(FULLM, v1a);
                    unsigned m1o = __ballot_sync(FULLM, v1b);
                    unsigned m2e = __ballot_sync(FULLM, v2a);
                    unsigned m2o = __ballot_sync(FULLM, v2b);
                    if (c1[kp] < 16 && (m1e | m1o)) {
                        int re = __popc(m1e & lt)  + __popc(m1o & lt);
                        int ro = __popc(m1e & lte) + __popc(m1o & lt);
                        if (v1a && c1[kp] + re < 16) sidx[w][kp][0][c1[kp]+re] = gi;
                        if (v1b && c1[kp] + ro < 16) sidx[w][kp][0][c1[kp]+ro] = gi + 1;
                        c1[kp] = min(c1[kp] + __popc(m1e) + __popc(m1o), 16);
                    }
                    if (c2[kp] < 16 && (m2e | m2o)) {
                        int re = __popc(m2e & lt)  + __popc(m2o & lt);
                        int ro = __popc(m2e & lte) + __popc(m2o & lt);
                        if (v2a && c2[kp] + re < 16) sidx[w][kp][1][c2[kp]+re] = gi;
                        if (v2b && c2[kp] + ro < 16) sidx[w][kp][1][c2[kp]+ro] = gi + 1;
                        c2[kp] = min(c2[kp] + __popc(m2e) + __popc(m2o), 16);
                    }
                }
                if (c1[0] >= 16 && c2[0] >= 16 && c1[1] >= 16 && c2[1] >= 16) break;
            }
        }
    }
    __syncwarp();
    int rI = lane >> 4, s = lane & 15;
    #pragma unroll
    for (int kp = 0; kp < 2; kp++) {
        int row = row0 + kp;
        if (lane < 2) g_ballcnt[row*2 + lane] = lane ? c2[kp] : c1[kp];
        int cnt = rI ? c2[kp] : c1[kp];
        g_ballidx[row*32 + lane] = (s < cnt) ? sidx[w][kp][rI][s]
                                             : (cnt > 0 ? sidx[w][kp][rI][0] : 0);
    }
}

// ==================================================================
// mlpgemm: SA MLP + maxpool + GEMM [4,288]@[288,128] + BN + ReLU
// ==================================================================
__global__ void __launch_bounds__(128) mlpgemm_kernel(
        const float* __restrict__ w0, const float* __restrict__ bn0,
        const float* __restrict__ w1, const float* __restrict__ bn1,
        const float* __restrict__ fw, const float* __restrict__ fbn,
        float* __restrict__ feats, float* __restrict__ out) {
    __shared__ float sr[4*288];
    __shared__ float sw0[128];
    __shared__ float sw1[512];
    __shared__ float sb0s[32], sb0m[32], sb0b[32];
    __shared__ float sb1s[32], sb1m[32], sb1b[32];
    int tid = threadIdx.x;
    int row0 = blockIdx.x*4;
    int b = row0 >> 11;

    sw0[tid] = w0[tid];
    #pragma unroll
    for (int i = 0; i < 4; i++) sw1[tid + i*128] = w1[tid + i*128];
    if (tid < 32) {
        int br = tid >> 4, c = tid & 15;
        float g = bn0[br*64 + c], be = bn0[br*64+16+c], m = bn0[br*64+32+c], v = bn0[br*64+48+c];
        sb0s[tid] = g * (1.0f/sqrtf(v + 1e-5f)); sb0m[tid] = m; sb0b[tid] = be;
        g = bn1[br*64 + c]; be = bn1[br*64+16+c]; m = bn1[br*64+32+c]; v = bn1[br*64+48+c];
        sb1s[tid] = g * (1.0f/sqrtf(v + 1e-5f)); sb1m[tid] = m; sb1b[tid] = be;
    }
    // load bev features for the 4 rows
    #pragma unroll
    for (int r = 0; r < 4; r++) {
        #pragma unroll
        for (int h = 0; h < 2; h++)
            sr[r*288 + tid + h*128] = feats[(size_t)(row0 + r)*288 + tid + h*128];
    }
    __syncthreads();

    // ---- SA MLP + maxpool (8 groups of 16 threads) ----
    {
        int g = tid >> 4;            // 0..7 = (row 0..3) x (radius 0..1)
        int r = g >> 1, rI = g & 1, s = tid & 15;
        int row = row0 + r;
        float kx = g_kp[row*3], ky = g_kp[row*3+1], kz = g_kp[row*3+2];
        const float4* P = g_pts + (size_t)b*NPTS;
        int cnt = g_ballcnt[row*2 + rI];
        float gx = 0.f, gy = 0.f, gz = 0.f, gi = 0.f;
        if (cnt > 0) {
            int id = g_ballidx[row*32 + rI*16 + ((s < cnt) ? s : 0)];
            float4 p = P[id];
            gx = p.x - kx; gy = p.y - ky; gz = p.z - kz; gi = p.w;
        }
        const float* W0  = sw0  + rI*64;
        const float* W1  = sw1  + rI*256;
        const float* B0s = sb0s + rI*16; const float* B0m = sb0m + rI*16; const float* B0b = sb0b + rI*16;
        const float* B1s = sb1s + rI*16; const float* B1m = sb1m + rI*16; const float* B1b = sb1b + rI*16;

        float h1[16];
        #pragma unroll
        for (int c = 0; c < 16; c++) {
            float a = gx*W0[c] + gy*W0[16+c] + gz*W0[32+c] + gi*W0[48+c];
            h1[c] = fmaxf((a - B0m[c])*B0s[c] + B0b[c], 0.0f);
        }
        float h2[16];
        #pragma unroll
        for (int c = 0; c < 16; c++) {
            float a = 0.f;
            #pragma unroll
            for (int k = 0; k < 16; k++) a += h1[k]*W1[k*16 + c];
            h2[c] = fmaxf((a - B1m[c])*B1s[c] + B1b[c], 0.0f);
        }
        #pragma unroll
        for (int off = 8; off; off >>= 1) {   // maxpool within 16-lane group
            #pragma unroll
            for (int c = 0; c < 16; c++)
                h2[c] = fmaxf(h2[c], __shfl_xor_sync(FULLM, h2[c], off));
        }
        if (s == 0) {
            #pragma unroll
            for (int c = 0; c < 16; c++) {
                sr[r*288 + 256 + rI*16 + c] = h2[c];
                feats[(size_t)row*288 + 256 + rI*16 + c] = h2[c];
            }
        }
    }
    __syncthreads();

    // ---- GEMM [4,288]@[288,128] + BN + ReLU ----
    float acc[4] = {0.f, 0.f, 0.f, 0.f};
    for (int k = 0; k < 288; k++) {
        float wv = __ldg(fw + (size_t)k*128 + tid);
        #pragma unroll
        for (int r = 0; r < 4; r++) acc[r] += sr[r*288 + k] * wv;
    }
    float g = fbn[tid], be = fbn[128+tid], m = fbn[256+tid], v = fbn[384+tid];
    float sc = g * (1.0f/sqrtf(v + 1e-5f));
    #pragma unroll
    for (int r = 0; r < 4; r++)
        out[(size_t)(row0 + r)*128 + tid] = fmaxf((acc[r] - m)*sc + be, 0.f);
}

// ---------------- launch ----------------
extern "C" void kernel_launch(void* const* d_in, const int* in_sizes, int n_in,
                              void* d_out, int out_size) {
    const float* points = (const float*)d_in[0];
    const float* rng    = (const float*)d_in[1];
    const float* sf     = (const float*)d_in[2];
    const float* sa_w0  = (const float*)d_in[3];
    const float* sa_bn0 = (const float*)d_in[4];
    const float* sa_w1  = (const float*)d_in[5];
    const float* sa_bn1 = (const float*)d_in[6];
    const float* fw     = (const float*)d_in[7];
    const float* fbn    = (const float*)d_in[8];
    float* out = (float*)d_out;

    float* fused  = out;                                          // [4096,128]
    float* feats  = out + (size_t)NROWS*128;                      // [4096,288]
    float* coords = out + (size_t)NROWS*128 + (size_t)NROWS*288;  // [4096,4]

    const int FPS_SMEM = CMPN * sizeof(float4);   // 128 KB
    cudaFuncSetAttribute(fps_kernel, cudaFuncAttributeMaxDynamicSharedMemorySize, FPS_SMEM);

    fps_kernel<<<64, 256, FPS_SMEM>>>(points, rng, coords);
    bevscan_kernel<<<SCANBLK + NROWS/2, 512>>>(sf, feats);
    mlpgemm_kernel<<<NROWS/4, 128>>>(sa_w0, sa_bn0, sa_w1, sa_bn1, fw, fbn, feats, fused);
}

// round 7
// speedup vs baseline: 1.1344x; 1.1344x over previous
#include <cuda_runtime.h>
#include <math.h>

#define NPTS   16384
#define BATCH  2
#define HBEV   200
#define WBEV   176
#define CBEV   256
#define HW     (HBEV*WBEV)
#define KTOT   2048
#define NROWS  (BATCH*KTOT)
#define CMPN   8192
#define FULLM  0xffffffffu
#define SCANBLK 128

// ---------------- static device scratch ----------------
__device__ float4 g_pts[BATCH*NPTS];       // SoA points: x,y,z,intensity
__device__ float  g_kp[NROWS*3];           // keypoint coords
__device__ int    g_ballidx[NROWS*32];     // [row][2][16] neighbor indices
__device__ int    g_ballcnt[NROWS*2];      // [row][2] capped counts

// ---------------- packed f32x2 + redux helpers ----------------
__device__ __forceinline__ unsigned long long pk2(float lo, float hi) {
    unsigned long long r; asm("mov.b64 %0, {%1, %2};" : "=l"(r) : "f"(lo), "f"(hi)); return r;
}
__device__ __forceinline__ void upk2(unsigned long long v, float& lo, float& hi) {
    asm("mov.b64 {%0, %1}, %2;" : "=f"(lo), "=f"(hi) : "l"(v));
}
__device__ __forceinline__ unsigned long long addx2(unsigned long long a, unsigned long long b) {
    unsigned long long r; asm("add.rn.f32x2 %0, %1, %2;" : "=l"(r) : "l"(a), "l"(b)); return r;
}
__device__ __forceinline__ unsigned long long mulx2(unsigned long long a, unsigned long long b) {
    unsigned long long r; asm("mul.rn.f32x2 %0, %1, %2;" : "=l"(r) : "l"(a), "l"(b)); return r;
}
__device__ __forceinline__ unsigned redux_maxu(unsigned v) {
    unsigned r; asm("redux.sync.max.u32 %0, %1, 0xffffffff;" : "=r"(r) : "r"(v)); return r;
}
__device__ __forceinline__ unsigned redux_minu(unsigned v) {
    unsigned r; asm("redux.sync.min.u32 %0, %1, 0xffffffff;" : "=r"(r) : "r"(v)); return r;
}
__device__ __forceinline__ unsigned long long umax64(unsigned long long a, unsigned long long b) {
    return (a > b) ? a : b;
}

// ==================================================================
// FPS: compaction + sampling (blocks 0..5) + SoA prep (blocks 6..63)
// Reduction: warp redux pair -> packed-u64 STS -> BAR -> register max-tree
// ==================================================================
template<int P>
__device__ __forceinline__ void fps_body(int b, int K, int kpbase, int M,
                                         float* __restrict__ coords_out,
                                         unsigned long long (*s_pack)[8]) {
    extern __shared__ float4 scmp[];
    int t = threadIdx.x;
    int lane = t & 31, warp = t >> 5;

    unsigned long long Xn[P], Yn[P], Zn[P];   // negated coords
    float D[2*P];
    #pragma unroll
    for (int p = 0; p < P; p++) {
        float4 a = scmp[(2*p)*256 + t];
        float4 c = scmp[(2*p+1)*256 + t];
        Xn[p] = pk2(-a.x, -c.x); Yn[p] = pk2(-a.y, -c.y); Zn[p] = pk2(-a.z, -c.z);
        D[2*p]   = ((2*p)*256 + t   < M) ? 1e10f : -1.0f;
        D[2*p+1] = ((2*p+1)*256 + t < M) ? 1e10f : -1.0f;
    }

    int sel = 0;   // first valid point = compacted index 0
    for (int k = 0; ; k++) {
        float4 w = scmp[sel];                // LDS broadcast
        if (t == 0) {
            int r = kpbase + k;
            g_kp[r*3+0] = w.x; g_kp[r*3+1] = w.y; g_kp[r*3+2] = w.z;
            coords_out[r*4+0] = (float)b;
            coords_out[r*4+1] = w.x; coords_out[r*4+2] = w.y; coords_out[r*4+3] = w.z;
        }
        if (k == K-1) break;

        unsigned long long wx = pk2(w.x, w.x);
        unsigned long long wy = pk2(w.y, w.y);
        unsigned long long wz = pk2(w.z, w.z);
        float best = -1.0f; int bi = 0x7fffffff;
        #pragma unroll
        for (int p = 0; p < P; p++) {
            unsigned long long dx = addx2(Xn[p], wx);   // (w-x): square == (x-w)^2 exactly
            unsigned long long dy = addx2(Yn[p], wy);
            unsigned long long dz = addx2(Zn[p], wz);
            unsigned long long d2 = addx2(addx2(mulx2(dx,dx), mulx2(dy,dy)), mulx2(dz,dz));
            float dl, dh; upk2(d2, dl, dh);
            float n0 = fminf(D[2*p],   dl); D[2*p]   = n0;
            float n1 = fminf(D[2*p+1], dh); D[2*p+1] = n1;
            // ascending slot order + strict '>' keeps smallest index on intra-thread ties
            if (n0 > best) { best = n0; bi = (2*p)*256 + t; }
            if (n1 > best) { best = n1; bi = (2*p+1)*256 + t; }
        }
        best = fmaxf(best, 0.0f);             // invalid threads: best=0, bi stays huge
        unsigned u  = __float_as_uint(best);  // d>=0 => bits order-isomorphic
        unsigned vm = redux_maxu(u);
        unsigned cand = (u == vm) ? (unsigned)bi : 0x7fffffffu;
        unsigned im = redux_minu(cand);
        int par = k & 1;
        if (lane == 0)
            s_pack[par][warp] = ((unsigned long long)vm << 32) | (unsigned)(~im);
        __syncthreads();
        // every thread: max over the 8 packed (val,~idx) — higher val wins, tie -> lower idx
        const ulonglong2* sp = (const ulonglong2*)s_pack[par];
        ulonglong2 q0 = sp[0], q1 = sp[1], q2 = sp[2], q3 = sp[3];
        unsigned long long m0 = umax64(umax64(q0.x, q0.y), umax64(q1.x, q1.y));
        unsigned long long m1 = umax64(umax64(q2.x, q2.y), umax64(q3.x, q3.y));
        unsigned long long mm = umax64(m0, m1);
        sel = (int)(~(unsigned)(mm & 0xffffffffu));
    }
}

__global__ void __launch_bounds__(256,1) fps_kernel(const float* __restrict__ pts,
                                                    const float* __restrict__ rng,
                                                    float* __restrict__ coords_out) {
    extern __shared__ float4 scmp[];
    __shared__ __align__(16) unsigned long long s_pack[2][8];
    __shared__ int wsum[8];
    __shared__ int s_tot;

    int t = threadIdx.x;
    if (blockIdx.x >= 6) {
        // ---- SoA prep on otherwise-idle SMs ----
        for (int i = ((int)blockIdx.x - 6)*256 + t; i < BATCH*NPTS; i += 58*256) {
            const float* p = pts + (size_t)i*5;
            g_pts[i] = make_float4(p[1], p[2], p[3], p[4]);
        }
        return;
    }

    int run = blockIdx.x, b = run/3, band = run - b*3;
    int lane = t & 31, warp = t >> 5;

    // ---- stable band compaction: 64 points per thread (contiguous) ----
    const float4* R4 = (const float4*)(rng + (size_t)b*NPTS) + t*16;
    unsigned long long bits = 0; int cnt = 0;
    #pragma unroll
    for (int q = 0; q < 16; q++) {
        float4 r4 = R4[q];
        float rr[4] = {r4.x, r4.y, r4.z, r4.w};
        #pragma unroll
        for (int u = 0; u < 4; u++) {
            float r = rr[u];
            bool sh = (r > 0.0f) && (r < 25.0f);
            bool lg = (r > 45.0f);
            bool v = (band == 0) ? sh : ((band == 2) ? lg : (!lg && !sh));
            if (v) { bits |= (1ull << (q*4+u)); cnt++; }
        }
    }
    int inc = cnt;
    #pragma unroll
    for (int off = 1; off < 32; off <<= 1) {
        int o = __shfl_up_sync(FULLM, inc, off);
        if (lane >= off) inc += o;
    }
    if (lane == 31) wsum[warp] = inc;
    __syncthreads();
    if (warp == 0 && lane < 8) {
        int v = wsum[lane];
        #pragma unroll
        for (int off = 1; off < 8; off <<= 1) {
            int o = __shfl_up_sync(0xffu, v, off);
            if (lane >= off) v += o;
        }
        wsum[lane] = v;
        if (lane == 7) s_tot = v;
    }
    __syncthreads();
    int off0 = inc - cnt + (warp ? wsum[warp-1] : 0);
    const float* PP = pts + (size_t)b*NPTS*5;
    for (int u = 0; u < 64; u++) {
        if ((bits >> u) & 1ull) {
            if (off0 < CMPN) {
                const float* p = PP + (size_t)(t*64 + u)*5;
                scmp[off0] = make_float4(p[1], p[2], p[3], p[4]);
            }
            off0++;
        }
    }
    int M = min(s_tot, CMPN);
    for (int i = M + t; i < CMPN; i += 256)
        scmp[i] = make_float4(1e15f, 1e15f, 1e15f, 0.f);
    __syncthreads();

    // ---- FPS dispatch sized to the band population ----
    int K = (band == 0) ? 1024 : 512;
    int kpbase = b*KTOT + (band==0 ? 0 : (band==1 ? 1024 : 1536));
    int P = min(16, ((M + 1023) >> 10) * 2);   // even, 512*P >= M
    switch (P) {
        case 2:  fps_body<2>(b, K, kpbase, M, coords_out, s_pack); break;
        case 4:  fps_body<4>(b, K, kpbase, M, coords_out, s_pack); break;
        case 6:  fps_body<6>(b, K, kpbase, M, coords_out, s_pack); break;
        case 8:  fps_body<8>(b, K, kpbase, M, coords_out, s_pack); break;
        case 10: fps_body<10>(b, K, kpbase, M, coords_out, s_pack); break;
        case 12: fps_body<12>(b, K, kpbase, M, coords_out, s_pack); break;
        case 14: fps_body<14>(b, K, kpbase, M, coords_out, s_pack); break;
        default: fps_body<16>(b, K, kpbase, M, coords_out, s_pack); break;
    }
}

// ==================================================================
// bevscan: ball-query scan (blocks 0..127) + BEV bilinear (blocks 128..)
// ==================================================================
__global__ void __launch_bounds__(512) bevscan_kernel(const float* __restrict__ sf,
                                                      float* __restrict__ feats) {
    __shared__ float2 sx[1024], sy[1024], sz[1024];
    __shared__ int sidx[16][2][2][16];     // [warp][kp][radius][slot]
    int tid = threadIdx.x;

    if (blockIdx.x >= SCANBLK) {
        // ---- BEV bilinear: 2 rows per block, direct CHW gather ----
        int row = ((int)blockIdx.x - SCANBLK)*2 + (tid >> 8);
        int c = tid & 255;
        int b = row >> 11;
        float kx = g_kp[row*3+0], ky = g_kp[row*3+1];
        float xi = ((kx - 0.0f)     / 0.05f) / 8.0f;
        float yi = ((ky - (-40.0f)) / 0.05f) / 8.0f;
        int x0 = (int)floorf(xi); int x1 = x0 + 1;
        int y0 = (int)floorf(yi); int y1 = y0 + 1;
        x0 = min(max(x0, 0), WBEV-1); x1 = min(max(x1, 0), WBEV-1);
        y0 = min(max(y0, 0), HBEV-1); y1 = min(max(y1, 0), HBEV-1);
        float x0f = (float)x0, x1f = (float)x1, y0f = (float)y0, y1f = (float)y1;
        float wa = (x1f - xi)*(y1f - yi);
        float wb = (x1f - xi)*(yi - y0f);
        float wc = (xi - x0f)*(y1f - yi);
        float wd = (xi - x0f)*(yi - y0f);
        const float* ch = sf + ((size_t)b*CBEV + c)*HW;
        float Ia = __ldg(ch + y0*WBEV + x0);
        float Ib = __ldg(ch + y1*WBEV + x0);
        float Ic = __ldg(ch + y0*WBEV + x1);
        float Id = __ldg(ch + y1*WBEV + x1);
        feats[(size_t)row*288 + c] = Ia*wa + Ib*wb + Ic*wc + Id*wd;
        return;
    }

    // ---- ball-query scan: 2 keypoints per warp, SoA float2 tiles ----
    int w = tid >> 5, lane = tid & 31;
    int row0 = blockIdx.x*32 + w*2;
    int b = row0 >> 11;
    const float4* P = g_pts + (size_t)b*NPTS;

    unsigned long long nkx[2], nky[2], nkz[2];
    #pragma unroll
    for (int kp = 0; kp < 2; kp++) {
        float kx = g_kp[(row0+kp)*3], ky = g_kp[(row0+kp)*3+1], kz = g_kp[(row0+kp)*3+2];
        nkx[kp] = pk2(-kx, -kx); nky[kp] = pk2(-ky, -ky); nkz[kp] = pk2(-kz, -kz);
    }
    unsigned lt  = (1u << lane) - 1u;
    unsigned lte = lt | (1u << lane);

    int c1[2] = {0,0}, c2[2] = {0,0};
    for (int base0 = 0; base0 < NPTS; base0 += 2048) {
        __syncthreads();
        #pragma unroll
        for (int i = 0; i < 2; i++) {
            int j = tid + i*512;            // float2 slot
            float4 p0 = P[base0 + 2*j];
            float4 p1 = P[base0 + 2*j + 1];
            sx[j] = make_float2(p0.x, p1.x);
            sy[j] = make_float2(p0.y, p1.y);
            sz[j] = make_float2(p0.z, p1.z);
        }
        __syncthreads();
        if (c1[0] >= 16 && c2[0] >= 16 && c1[1] >= 16 && c2[1] >= 16) continue;
        for (int o32 = 0; o32 < 1024; o32 += 32) {
            float2 vx = sx[o32 + lane], vy = sy[o32 + lane], vz = sz[o32 + lane];
            unsigned long long px = pk2(vx.x, vx.y);
            unsigned long long py = pk2(vy.x, vy.y);
            unsigned long long pz = pk2(vz.x, vz.y);
            float da[2], db[2];
            #pragma unroll
            for (int kp = 0; kp < 2; kp++) {
                unsigned long long dx = addx2(px, nkx[kp]);
                unsigned long long dy = addx2(py, nky[kp]);
                unsigned long long dz = addx2(pz, nkz[kp]);
                unsigned long long d2 = addx2(addx2(mulx2(dx,dx), mulx2(dy,dy)), mulx2(dz,dz));
                upk2(d2, da[kp], db[kp]);
            }
            bool any = (da[0] < 4.0f) || (db[0] < 4.0f) || (da[1] < 4.0f) || (db[1] < 4.0f);
            if (__ballot_sync(FULLM, any)) {
                int gi = base0 + 2*(o32 + lane);
                #pragma unroll
                for (int kp = 0; kp < 2; kp++) {
                    bool v2a = da[kp] < 4.0f, v2b = db[kp] < 4.0f;
                    bool v1a = da[kp] < 1.0f, v1b = db[kp] < 1.0f;
                    unsigned m1e = __ballot_sync(FULLM, v1a);
                    unsigned m1o = __ballot_sync(FULLM, v1b);
                    unsigned m2e = __ballot_sync(FULLM, v2a);
                    unsigned m2o = __ballot_sync(FULLM, v2b);
                    if (c1[kp] < 16 && (m1e | m1o)) {
                        int re = __popc(m1e & lt)  + __popc(m1o & lt);
                        int ro = __popc(m1e & lte) + __popc(m1o & lt);
                        if (v1a && c1[kp] + re < 16) sidx[w][kp][0][c1[kp]+re] = gi;
                        if (v1b && c1[kp] + ro < 16) sidx[w][kp][0][c1[kp]+ro] = gi + 1;
                        c1[kp] = min(c1[kp] + __popc(m1e) + __popc(m1o), 16);
                    }
                    if (c2[kp] < 16 && (m2e | m2o)) {
                        int re = __popc(m2e & lt)  + __popc(m2o & lt);
                        int ro = __popc(m2e & lte) + __popc(m2o & lt);
                        if (v2a && c2[kp] + re < 16) sidx[w][kp][1][c2[kp]+re] = gi;
                        if (v2b && c2[kp] + ro < 16) sidx[w][kp][1][c2[kp]+ro] = gi + 1;
                        c2[kp] = min(c2[kp] + __popc(m2e) + __popc(m2o), 16);
                    }
                }
                if (c1[0] >= 16 && c2[0] >= 16 && c1[1] >= 16 && c2[1] >= 16) break;
            }
        }
    }
    __syncwarp();
    int rI = lane >> 4, s = lane & 15;
    #pragma unroll
    for (int kp = 0; kp < 2; kp++) {
        int row = row0 + kp;
        if (lane < 2) g_ballcnt[row*2 + lane] = lane ? c2[kp] : c1[kp];
        int cnt = rI ? c2[kp] : c1[kp];
        g_ballidx[row*32 + lane] = (s < cnt) ? sidx[w][kp][rI][s]
                                             : (cnt > 0 ? sidx[w][kp][rI][0] : 0);
    }
}

// ==================================================================
// mlpgemm: SA MLP + maxpool + GEMM [4,288]@[288,128] + BN + ReLU
// ==================================================================
__global__ void __launch_bounds__(128) mlpgemm_kernel(
        const float* __restrict__ w0, const float* __restrict__ bn0,
        const float* __restrict__ w1, const float* __restrict__ bn1,
        const float* __restrict__ fw, const float* __restrict__ fbn,
        float* __restrict__ feats, float* __restrict__ out) {
    __shared__ float sr[4*288];
    __shared__ float sw0[128];
    __shared__ float sw1[512];
    __shared__ float sb0s[32], sb0m[32], sb0b[32];
    __shared__ float sb1s[32], sb1m[32], sb1b[32];
    int tid = threadIdx.x;
    int row0 = blockIdx.x*4;
    int b = row0 >> 11;

    sw0[tid] = w0[tid];
    #pragma unroll
    for (int i = 0; i < 4; i++) sw1[tid + i*128] = w1[tid + i*128];
    if (tid < 32) {
        int br = tid >> 4, c = tid & 15;
        float g = bn0[br*64 + c], be = bn0[br*64+16+c], m = bn0[br*64+32+c], v = bn0[br*64+48+c];
        sb0s[tid] = g * (1.0f/sqrtf(v + 1e-5f)); sb0m[tid] = m; sb0b[tid] = be;
        g = bn1[br*64 + c]; be = bn1[br*64+16+c]; m = bn1[br*64+32+c]; v = bn1[br*64+48+c];
        sb1s[tid] = g * (1.0f/sqrtf(v + 1e-5f)); sb1m[tid] = m; sb1b[tid] = be;
    }
    // load bev features for the 4 rows
    #pragma unroll
    for (int r = 0; r < 4; r++) {
        #pragma unroll
        for (int h = 0; h < 2; h++)
            sr[r*288 + tid + h*128] = feats[(size_t)(row0 + r)*288 + tid + h*128];
    }
    __syncthreads();

    // ---- SA MLP + maxpool (8 groups of 16 threads) ----
    {
        int g = tid >> 4;            // 0..7 = (row 0..3) x (radius 0..1)
        int r = g >> 1, rI = g & 1, s = tid & 15;
        int row = row0 + r;
        float kx = g_kp[row*3], ky = g_kp[row*3+1], kz = g_kp[row*3+2];
        const float4* P = g_pts + (size_t)b*NPTS;
        int cnt = g_ballcnt[row*2 + rI];
        float gx = 0.f, gy = 0.f, gz = 0.f, gi = 0.f;
        if (cnt > 0) {
            int id = g_ballidx[row*32 + rI*16 + ((s < cnt) ? s : 0)];
            float4 p = P[id];
            gx = p.x - kx; gy = p.y - ky; gz = p.z - kz; gi = p.w;
        }
        const float* W0  = sw0  + rI*64;
        const float* W1  = sw1  + rI*256;
        const float* B0s = sb0s + rI*16; const float* B0m = sb0m + rI*16; const float* B0b = sb0b + rI*16;
        const float* B1s = sb1s + rI*16; const float* B1m = sb1m + rI*16; const float* B1b = sb1b + rI*16;

        float h1[16];
        #pragma unroll
        for (int c = 0; c < 16; c++) {
            float a = gx*W0[c] + gy*W0[16+c] + gz*W0[32+c] + gi*W0[48+c];
            h1[c] = fmaxf((a - B0m[c])*B0s[c] + B0b[c], 0.0f);
        }
        float h2[16];
        #pragma unroll
        for (int c = 0; c < 16; c++) {
            float a = 0.f;
            #pragma unroll
            for (int k = 0; k < 16; k++) a += h1[k]*W1[k*16 + c];
            h2[c] = fmaxf((a - B1m[c])*B1s[c] + B1b[c], 0.0f);
        }
        #pragma unroll
        for (int off = 8; off; off >>= 1) {   // maxpool within 16-lane group
            #pragma unroll
            for (int c = 0; c < 16; c++)
                h2[c] = fmaxf(h2[c], __shfl_xor_sync(FULLM, h2[c], off));
        }
        if (s == 0) {
            #pragma unroll
            for (int c = 0; c < 16; c++) {
                sr[r*288 + 256 + rI*16 + c] = h2[c];
                feats[(size_t)row*288 + 256 + rI*16 + c] = h2[c];
            }
        }
    }
    __syncthreads();

    // ---- GEMM [4,288]@[288,128] + BN + ReLU ----
    float acc[4] = {0.f, 0.f, 0.f, 0.f};
    for (int k = 0; k < 288; k++) {
        float wv = __ldg(fw + (size_t)k*128 + tid);
        #pragma unroll
        for (int r = 0; r < 4; r++) acc[r] += sr[r*288 + k] * wv;
    }
    float g = fbn[tid], be = fbn[128+tid], m = fbn[256+tid], v = fbn[384+tid];
    float sc = g * (1.0f/sqrtf(v + 1e-5f));
    #pragma unroll
    for (int r = 0; r < 4; r++)
        out[(size_t)(row0 + r)*128 + tid] = fmaxf((acc[r] - m)*sc + be, 0.f);
}

// ---------------- launch ----------------
extern "C" void kernel_launch(void* const* d_in, const int* in_sizes, int n_in,
                              void* d_out, int out_size) {
    const float* points = (const float*)d_in[0];
    const float* rng    = (const float*)d_in[1];
    const float* sf     = (const float*)d_in[2];
    const float* sa_w0  = (const float*)d_in[3];
    const float* sa_bn0 = (const float*)d_in[4];
    const float* sa_w1  = (const float*)d_in[5];
    const float* sa_bn1 = (const float*)d_in[6];
    const float* fw     = (const float*)d_in[7];
    const float* fbn    = (const float*)d_in[8];
    float* out = (float*)d_out;

    float* fused  = out;                                          // [4096,128]
    float* feats  = out + (size_t)NROWS*128;                      // [4096,288]
    float* coords = out + (size_t)NROWS*128 + (size_t)NROWS*288;  // [4096,4]

    const int FPS_SMEM = CMPN * sizeof(float4);   // 128 KB
    cudaFuncSetAttribute(fps_kernel, cudaFuncAttributeMaxDynamicSharedMemorySize, FPS_SMEM);

    fps_kernel<<<64, 256, FPS_SMEM>>>(points, rng, coords);
    bevscan_kernel<<<SCANBLK + NROWS/2, 512>>>(sf, feats);
    mlpgemm_kernel<<<NROWS/4, 128>>>(sa_w0, sa_bn0, sa_w1, sa_bn1, fw, fbn, feats, fused);
}